// round 1
// baseline (speedup 1.0000x reference)
#include <cuda_runtime.h>

#define NN 50000
#define NE 800000
#define NGR 512
#define BN_EPS 1e-5f

// ---------------- scratch (static __device__ — no allocations) ----------------
__device__ float4 g_agg[NN * 16];
__device__ float4 g_z1 [NN * 16];
__device__ float4 g_z2 [NN * 16];
__device__ float4 g_hA [NN * 16];
__device__ float4 g_hB [NN * 16];
__device__ float  g_stats[128];        // [0:64) sum -> scale, [64:128) sumsq -> shift
__device__ float4 g_pool[NGR * 16];    // [G, 64]
__device__ float  g_mid [NGR * 128];   // [G, 128]

// ---------------- kernels ----------------

__global__ void k_copy4(const float4* __restrict__ src, float4* __restrict__ dst, int n) {
    int i = blockIdx.x * blockDim.x + threadIdx.x;
    if (i < n) dst[i] = src[i];
}

__global__ void k_zero(float* __restrict__ p, int n) {
    int i = blockIdx.x * blockDim.x + threadIdx.x;
    if (i < n) p[i] = 0.0f;
}

// agg[dst] += h[src], vector-atomic float4 (16 slices of 4 floats per edge)
__global__ void k_scatter(const int* __restrict__ ei,
                          const float4* __restrict__ h,
                          float4* __restrict__ agg) {
    int t = blockIdx.x * blockDim.x + threadIdx.x;
    if (t >= NE * 16) return;
    int e = t >> 4;
    int j = t & 15;
    int src = ei[e];
    int dst = ei[NE + e];
    float4 v = h[src * 16 + j];
    atomicAdd(&agg[dst * 16 + j], v);
}

// C[rows,64] = relu(A[rows,64] @ W[64,64] + bias)
__global__ void k_gemm64_relu(const float* __restrict__ A, const float* __restrict__ W,
                              const float* __restrict__ bias, float* __restrict__ C,
                              int rows) {
    __shared__ float Ws[64 * 64];
    __shared__ float As[64 * 65];   // padded to kill bank conflicts
    int t = threadIdx.x;            // 256 threads
    int row0 = blockIdx.x * 64;

    for (int i = t; i < 4096; i += 256) Ws[i] = W[i];
    for (int i = t; i < 4096; i += 256) {
        int r = row0 + (i >> 6);
        As[(i >> 6) * 65 + (i & 63)] = (r < rows) ? A[r * 64 + (i & 63)] : 0.0f;
    }
    __syncthreads();

    int lr = t >> 2;          // local row 0..63
    int cb = (t & 3) * 16;    // column base 0/16/32/48
    float acc[16];
#pragma unroll
    for (int j = 0; j < 16; j++) acc[j] = bias[cb + j];

#pragma unroll 4
    for (int k = 0; k < 64; k++) {
        float a = As[lr * 65 + k];
        const float4* w4 = (const float4*)&Ws[k * 64 + cb];
#pragma unroll
        for (int j = 0; j < 4; j++) {
            float4 w = w4[j];
            acc[j * 4 + 0] += a * w.x;
            acc[j * 4 + 1] += a * w.y;
            acc[j * 4 + 2] += a * w.z;
            acc[j * 4 + 3] += a * w.w;
        }
    }

    int r = row0 + lr;
    if (r < rows) {
#pragma unroll
        for (int j = 0; j < 16; j++)
            C[r * 64 + cb + j] = fmaxf(acc[j], 0.0f);
    }
}

// per-column sum and sumsq over [NN,64] -> stats[0:64), stats[64:128)
__global__ void k_colstats(const float* __restrict__ Z, float* __restrict__ stats) {
    int col = threadIdx.x & 63;
    int rep = threadIdx.x >> 6;   // 0..3
    float s = 0.0f, s2 = 0.0f;
    for (int r = blockIdx.x * 4 + rep; r < NN; r += gridDim.x * 4) {
        float v = Z[r * 64 + col];
        s += v;
        s2 += v * v;
    }
    __shared__ float sh[2][4][64];
    sh[0][rep][col] = s;
    sh[1][rep][col] = s2;
    __syncthreads();
    if (rep == 0) {
        s  = sh[0][0][col] + sh[0][1][col] + sh[0][2][col] + sh[0][3][col];
        s2 = sh[1][0][col] + sh[1][1][col] + sh[1][2][col] + sh[1][3][col];
        atomicAdd(&stats[col], s);
        atomicAdd(&stats[64 + col], s2);
    }
}

// stats -> scale/shift
__global__ void k_bnfinal(float* __restrict__ stats,
                          const float* __restrict__ gamma,
                          const float* __restrict__ beta) {
    int c = threadIdx.x;
    if (c >= 64) return;
    float mean = stats[c] * (1.0f / NN);
    float var  = stats[64 + c] * (1.0f / NN) - mean * mean;
    float sc = gamma[c] * rsqrtf(var + BN_EPS);
    stats[c] = sc;
    stats[64 + c] = beta[c] - mean * sc;
}

// hout = Z*scale + shift; optionally also seed next layer's agg with the same value
__global__ void k_bnapply(const float* __restrict__ Z, const float* __restrict__ stats,
                          float* __restrict__ hout, float* __restrict__ aggout) {
    int i = blockIdx.x * blockDim.x + threadIdx.x;
    if (i >= NN * 64) return;
    int c = i & 63;
    float v = Z[i] * stats[c] + stats[64 + c];
    hout[i] = v;
    if (aggout) aggout[i] = v;
}

// pool[batch[n]] += h[n]
__global__ void k_pool(const float4* __restrict__ h, const int* __restrict__ batch,
                       float4* __restrict__ pool) {
    int t = blockIdx.x * blockDim.x + threadIdx.x;
    if (t >= NN * 16) return;
    int n = t >> 4;
    int j = t & 15;
    atomicAdd(&pool[batch[n] * 16 + j], h[n * 16 + j]);
}

// tiny tail GEMMs: C[rows,M] = (relu?)(A[rows,K] @ W[K,M] + b)
template <int K, int M, bool RELU>
__global__ void k_smallgemm(const float* __restrict__ A, const float* __restrict__ W,
                            const float* __restrict__ b, float* __restrict__ C, int rows) {
    int idx = blockIdx.x * blockDim.x + threadIdx.x;
    if (idx >= rows * M) return;
    int r = idx / M, c = idx % M;
    float acc = b[c];
#pragma unroll 8
    for (int k = 0; k < K; k++) acc += A[r * K + k] * W[k * M + c];
    C[idx] = RELU ? fmaxf(acc, 0.0f) : acc;
}

// ---------------- launch ----------------

extern "C" void kernel_launch(void* const* d_in, const int* in_sizes, int n_in,
                              void* d_out, int out_size) {
    const float* x     = (const float*)d_in[0];
    const int*   ei    = (const int*)d_in[1];
    const int*   batch = (const int*)d_in[2];
    const float* prm[22];
    for (int i = 0; i < 22; i++) prm[i] = (const float*)d_in[3 + i];
    // prm layout: per layer L (L=0,1,2) at 6L: w_a,b_a,w_b,b_b,gamma,beta
    // prm[18]=w_lin0, prm[19]=b_lin0, prm[20]=w_fc1, prm[21]=b_fc1

    float *agg, *z1, *z2, *hA, *hB, *stats, *pool, *mid;
    cudaGetSymbolAddress((void**)&agg,   g_agg);
    cudaGetSymbolAddress((void**)&z1,    g_z1);
    cudaGetSymbolAddress((void**)&z2,    g_z2);
    cudaGetSymbolAddress((void**)&hA,    g_hA);
    cudaGetSymbolAddress((void**)&hB,    g_hB);
    cudaGetSymbolAddress((void**)&stats, g_stats);
    cudaGetSymbolAddress((void**)&pool,  g_pool);
    cudaGetSymbolAddress((void**)&mid,   g_mid);

    const int GEMM_BLOCKS = (NN + 63) / 64;       // 782
    const int SCAT_BLOCKS = (NE * 16) / 256;      // 50000
    const int ELT_BLOCKS  = (NN * 64) / 256;      // 12500
    const int CPY_BLOCKS  = (NN * 16 + 255) / 256;

    // -------- layer 1 (input x) --------
    k_copy4<<<CPY_BLOCKS, 256>>>((const float4*)x, (float4*)agg, NN * 16);
    k_scatter<<<SCAT_BLOCKS, 256>>>(ei, (const float4*)x, (float4*)agg);
    k_gemm64_relu<<<GEMM_BLOCKS, 256>>>(agg, prm[0], prm[1], z1, NN);
    k_gemm64_relu<<<GEMM_BLOCKS, 256>>>(z1, prm[2], prm[3], z2, NN);
    k_zero<<<1, 128>>>(stats, 128);
    k_colstats<<<512, 256>>>(z2, stats);
    k_bnfinal<<<1, 64>>>(stats, prm[4], prm[5]);
    k_bnapply<<<ELT_BLOCKS, 256>>>(z2, stats, hA, agg);   // hA = h1, agg pre-seeded

    // -------- layer 2 (input hA) --------
    k_scatter<<<SCAT_BLOCKS, 256>>>(ei, (const float4*)hA, (float4*)agg);
    k_gemm64_relu<<<GEMM_BLOCKS, 256>>>(agg, prm[6], prm[7], z1, NN);
    k_gemm64_relu<<<GEMM_BLOCKS, 256>>>(z1, prm[8], prm[9], z2, NN);
    k_zero<<<1, 128>>>(stats, 128);
    k_colstats<<<512, 256>>>(z2, stats);
    k_bnfinal<<<1, 64>>>(stats, prm[10], prm[11]);
    k_bnapply<<<ELT_BLOCKS, 256>>>(z2, stats, hB, agg);   // hB = h2

    // -------- layer 3 (input hB) --------
    k_scatter<<<SCAT_BLOCKS, 256>>>(ei, (const float4*)hB, (float4*)agg);
    k_gemm64_relu<<<GEMM_BLOCKS, 256>>>(agg, prm[12], prm[13], z1, NN);
    k_gemm64_relu<<<GEMM_BLOCKS, 256>>>(z1, prm[14], prm[15], z2, NN);
    k_zero<<<1, 128>>>(stats, 128);
    k_colstats<<<512, 256>>>(z2, stats);
    k_bnfinal<<<1, 64>>>(stats, prm[16], prm[17]);
    k_bnapply<<<ELT_BLOCKS, 256>>>(z2, stats, hA, nullptr);  // hA = h3

    // -------- pool + head --------
    k_zero<<<(NGR * 64 + 255) / 256, 256>>>(pool, NGR * 64);
    k_pool<<<CPY_BLOCKS, 256>>>((const float4*)hA, batch, (float4*)pool);
    k_smallgemm<64, 128, false><<<(NGR * 128 + 255) / 256, 256>>>(pool, prm[18], prm[19], mid, NGR);
    k_smallgemm<128, 64, true><<<(NGR * 64 + 255) / 256, 256>>>(mid, prm[20], prm[21], (float*)d_out, NGR);
}

// round 2
// speedup vs baseline: 2.1347x; 2.1347x over previous
#include <cuda_runtime.h>

#define NN 50000
#define NE 800000
#define NGR 512
#define BN_EPS 1e-5f

// ---------------- scratch (static __device__ — no allocations) ----------------
__device__ float4 g_agg[NN * 16];
__device__ float4 g_z1 [NN * 16];
__device__ float4 g_z2 [NN * 16];
__device__ float4 g_hA [NN * 16];
__device__ float4 g_hB [NN * 16];
__device__ float  g_stats[128];        // [0:64) sum -> scale, [64:128) sumsq -> shift
__device__ float4 g_pool[NGR * 16];    // [G, 64]
__device__ float  g_mid [NGR * 128];   // [G, 128]

// ---------------- kernels ----------------

__global__ void k_copy4(const float4* __restrict__ src, float4* __restrict__ dst, int n) {
    int i = blockIdx.x * blockDim.x + threadIdx.x;
    if (i < n) dst[i] = src[i];
}

__global__ void k_zero(float* __restrict__ p, int n) {
    int i = blockIdx.x * blockDim.x + threadIdx.x;
    if (i < n) p[i] = 0.0f;
}

// agg[dst] += h[src], vector-atomic float4 (16 slices of 4 floats per edge)
__global__ void k_scatter(const int* __restrict__ ei,
                          const float4* __restrict__ h,
                          float4* __restrict__ agg) {
    int t = blockIdx.x * blockDim.x + threadIdx.x;
    if (t >= NE * 16) return;
    int e = t >> 4;
    int j = t & 15;
    int src = ei[e];
    int dst = ei[NE + e];
    float4 v = h[src * 16 + j];
    atomicAdd(&agg[dst * 16 + j], v);
}

// C[rows,64] = relu(A[rows,64] @ W[64,64] + bias)
// Register-tiled: 256 threads, block tile 128 rows x 64 cols, thread tile 8x4.
// Per k-iter per thread: 1 LDS.128 (W) + 8 scalar broadcast LDS (A) -> 32 FFMA.
__global__ void __launch_bounds__(256) k_gemm64_relu(
        const float* __restrict__ A, const float* __restrict__ W,
        const float* __restrict__ bias, float* __restrict__ C, int rows) {
    __shared__ float Ws[64][64];   // [k][col], 16 KB
    __shared__ float As[128][68];  // [row][k], pad 68 keeps float4 align + kills conflicts
    int t = threadIdx.x;
    int row0 = blockIdx.x * 128;

    // load W (4096 floats = 1024 float4)
    for (int i = t; i < 1024; i += 256)
        ((float4*)Ws)[i] = ((const float4*)W)[i];
    // load A tile (128 rows x 16 float4), coalesced, conflict-free smem writes
    for (int i = t; i < 2048; i += 256) {
        int r = i >> 4, kc = i & 15;
        float4 v = make_float4(0.f, 0.f, 0.f, 0.f);
        if (row0 + r < rows) v = ((const float4*)A)[(row0 + r) * 16 + kc];
        *(float4*)&As[r][kc * 4] = v;
    }
    __syncthreads();

    int tx = t & 15;   // col group -> cols cb..cb+3
    int ty = t >> 4;   // row group -> rows rb..rb+7
    int cb = tx * 4;
    int rb = ty * 8;

    float4 bv = *(const float4*)&bias[cb];
    float acc[8][4];
#pragma unroll
    for (int i = 0; i < 8; i++) {
        acc[i][0] = bv.x; acc[i][1] = bv.y; acc[i][2] = bv.z; acc[i][3] = bv.w;
    }

#pragma unroll 8
    for (int k = 0; k < 64; k++) {
        float4 w = *(float4*)&Ws[k][cb];
#pragma unroll
        for (int i = 0; i < 8; i++) {
            float a = As[rb + i][k];
            acc[i][0] += a * w.x;
            acc[i][1] += a * w.y;
            acc[i][2] += a * w.z;
            acc[i][3] += a * w.w;
        }
    }

#pragma unroll
    for (int i = 0; i < 8; i++) {
        int r = row0 + rb + i;
        if (r < rows) {
            float4 o = make_float4(fmaxf(acc[i][0], 0.f), fmaxf(acc[i][1], 0.f),
                                   fmaxf(acc[i][2], 0.f), fmaxf(acc[i][3], 0.f));
            *(float4*)&C[r * 64 + cb] = o;
        }
    }
}

// per-column sum and sumsq over [NN,64] -> stats[0:64), stats[64:128)
__global__ void k_colstats(const float* __restrict__ Z, float* __restrict__ stats) {
    int col = threadIdx.x & 63;
    int rep = threadIdx.x >> 6;   // 0..3
    float s = 0.0f, s2 = 0.0f;
    for (int r = blockIdx.x * 4 + rep; r < NN; r += gridDim.x * 4) {
        float v = Z[r * 64 + col];
        s += v;
        s2 += v * v;
    }
    __shared__ float sh[2][4][64];
    sh[0][rep][col] = s;
    sh[1][rep][col] = s2;
    __syncthreads();
    if (rep == 0) {
        s  = sh[0][0][col] + sh[0][1][col] + sh[0][2][col] + sh[0][3][col];
        s2 = sh[1][0][col] + sh[1][1][col] + sh[1][2][col] + sh[1][3][col];
        atomicAdd(&stats[col], s);
        atomicAdd(&stats[64 + col], s2);
    }
}

// stats -> scale/shift
__global__ void k_bnfinal(float* __restrict__ stats,
                          const float* __restrict__ gamma,
                          const float* __restrict__ beta) {
    int c = threadIdx.x;
    if (c >= 64) return;
    float mean = stats[c] * (1.0f / NN);
    float var  = stats[64 + c] * (1.0f / NN) - mean * mean;
    float sc = gamma[c] * rsqrtf(var + BN_EPS);
    stats[c] = sc;
    stats[64 + c] = beta[c] - mean * sc;
}

// hout = Z*scale + shift; optionally also seed next layer's agg with the same value
__global__ void k_bnapply(const float* __restrict__ Z, const float* __restrict__ stats,
                          float* __restrict__ hout, float* __restrict__ aggout) {
    int i = blockIdx.x * blockDim.x + threadIdx.x;
    if (i >= NN * 64) return;
    int c = i & 63;
    float v = Z[i] * stats[c] + stats[64 + c];
    hout[i] = v;
    if (aggout) aggout[i] = v;
}

// pool[batch[n]] += h[n]
__global__ void k_pool(const float4* __restrict__ h, const int* __restrict__ batch,
                       float4* __restrict__ pool) {
    int t = blockIdx.x * blockDim.x + threadIdx.x;
    if (t >= NN * 16) return;
    int n = t >> 4;
    int j = t & 15;
    atomicAdd(&pool[batch[n] * 16 + j], h[n * 16 + j]);
}

// tiny tail GEMMs: C[rows,M] = (relu?)(A[rows,K] @ W[K,M] + b)
template <int K, int M, bool RELU>
__global__ void k_smallgemm(const float* __restrict__ A, const float* __restrict__ W,
                            const float* __restrict__ b, float* __restrict__ C, int rows) {
    int idx = blockIdx.x * blockDim.x + threadIdx.x;
    if (idx >= rows * M) return;
    int r = idx / M, c = idx % M;
    float acc = b[c];
#pragma unroll 8
    for (int k = 0; k < K; k++) acc += A[r * K + k] * W[k * M + c];
    C[idx] = RELU ? fmaxf(acc, 0.0f) : acc;
}

// ---------------- launch ----------------

extern "C" void kernel_launch(void* const* d_in, const int* in_sizes, int n_in,
                              void* d_out, int out_size) {
    const float* x     = (const float*)d_in[0];
    const int*   ei    = (const int*)d_in[1];
    const int*   batch = (const int*)d_in[2];
    const float* prm[22];
    for (int i = 0; i < 22; i++) prm[i] = (const float*)d_in[3 + i];
    // prm layout: per layer L (L=0,1,2) at 6L: w_a,b_a,w_b,b_b,gamma,beta
    // prm[18]=w_lin0, prm[19]=b_lin0, prm[20]=w_fc1, prm[21]=b_fc1

    float *agg, *z1, *z2, *hA, *hB, *stats, *pool, *mid;
    cudaGetSymbolAddress((void**)&agg,   g_agg);
    cudaGetSymbolAddress((void**)&z1,    g_z1);
    cudaGetSymbolAddress((void**)&z2,    g_z2);
    cudaGetSymbolAddress((void**)&hA,    g_hA);
    cudaGetSymbolAddress((void**)&hB,    g_hB);
    cudaGetSymbolAddress((void**)&stats, g_stats);
    cudaGetSymbolAddress((void**)&pool,  g_pool);
    cudaGetSymbolAddress((void**)&mid,   g_mid);

    const int GEMM_BLOCKS = (NN + 127) / 128;     // 391
    const int SCAT_BLOCKS = (NE * 16) / 256;      // 50000
    const int ELT_BLOCKS  = (NN * 64) / 256;      // 12500
    const int CPY_BLOCKS  = (NN * 16 + 255) / 256;

    // -------- layer 1 (input x) --------
    k_copy4<<<CPY_BLOCKS, 256>>>((const float4*)x, (float4*)agg, NN * 16);
    k_scatter<<<SCAT_BLOCKS, 256>>>(ei, (const float4*)x, (float4*)agg);
    k_gemm64_relu<<<GEMM_BLOCKS, 256>>>(agg, prm[0], prm[1], z1, NN);
    k_gemm64_relu<<<GEMM_BLOCKS, 256>>>(z1, prm[2], prm[3], z2, NN);
    k_zero<<<1, 128>>>(stats, 128);
    k_colstats<<<512, 256>>>(z2, stats);
    k_bnfinal<<<1, 64>>>(stats, prm[4], prm[5]);
    k_bnapply<<<ELT_BLOCKS, 256>>>(z2, stats, hA, agg);   // hA = h1, agg pre-seeded

    // -------- layer 2 (input hA) --------
    k_scatter<<<SCAT_BLOCKS, 256>>>(ei, (const float4*)hA, (float4*)agg);
    k_gemm64_relu<<<GEMM_BLOCKS, 256>>>(agg, prm[6], prm[7], z1, NN);
    k_gemm64_relu<<<GEMM_BLOCKS, 256>>>(z1, prm[8], prm[9], z2, NN);
    k_zero<<<1, 128>>>(stats, 128);
    k_colstats<<<512, 256>>>(z2, stats);
    k_bnfinal<<<1, 64>>>(stats, prm[10], prm[11]);
    k_bnapply<<<ELT_BLOCKS, 256>>>(z2, stats, hB, agg);   // hB = h2

    // -------- layer 3 (input hB) --------
    k_scatter<<<SCAT_BLOCKS, 256>>>(ei, (const float4*)hB, (float4*)agg);
    k_gemm64_relu<<<GEMM_BLOCKS, 256>>>(agg, prm[12], prm[13], z1, NN);
    k_gemm64_relu<<<GEMM_BLOCKS, 256>>>(z1, prm[14], prm[15], z2, NN);
    k_zero<<<1, 128>>>(stats, 128);
    k_colstats<<<512, 256>>>(z2, stats);
    k_bnfinal<<<1, 64>>>(stats, prm[16], prm[17]);
    k_bnapply<<<ELT_BLOCKS, 256>>>(z2, stats, hA, nullptr);  // hA = h3

    // -------- pool + head --------
    k_zero<<<(NGR * 64 + 255) / 256, 256>>>(pool, NGR * 64);
    k_pool<<<CPY_BLOCKS, 256>>>((const float4*)hA, batch, (float4*)pool);
    k_smallgemm<64, 128, false><<<(NGR * 128 + 255) / 256, 256>>>(pool, prm[18], prm[19], mid, NGR);
    k_smallgemm<128, 64, true><<<(NGR * 64 + 255) / 256, 256>>>(mid, prm[20], prm[21], (float*)d_out, NGR);
}

// round 3
// speedup vs baseline: 2.4031x; 1.1257x over previous
#include <cuda_runtime.h>

#define NN 50000
#define NE 800000
#define NGR 512
#define BN_EPS 1e-5f

// ---------------- scratch (static __device__ — no allocations) ----------------
__device__ float4 g_agg[NN * 16];
__device__ float4 g_z2 [NN * 16];
__device__ float4 g_hA [NN * 16];
__device__ float4 g_hB [NN * 16];
__device__ float  g_stats[128];        // [0:64) sum -> scale, [64:128) sumsq -> shift
__device__ float4 g_pool[NGR * 16];    // [G, 64]
__device__ float  g_mid [NGR * 128];   // [G, 128]

// ---------------- kernels ----------------

__global__ void k_copy4(const float4* __restrict__ src, float4* __restrict__ dst, int n) {
    int i = blockIdx.x * blockDim.x + threadIdx.x;
    if (i < n) dst[i] = src[i];
}

__global__ void k_zero(float* __restrict__ p, int n) {
    int i = blockIdx.x * blockDim.x + threadIdx.x;
    if (i < n) p[i] = 0.0f;
}

// agg[dst] += h[src], vector-atomic float4 (16 slices of 4 floats per edge)
__global__ void k_scatter(const int* __restrict__ ei,
                          const float4* __restrict__ h,
                          float4* __restrict__ agg) {
    int t = blockIdx.x * blockDim.x + threadIdx.x;
    if (t >= NE * 16) return;
    int e = t >> 4;
    int j = t & 15;
    int src = ei[e];
    int dst = ei[NE + e];
    float4 v = h[src * 16 + j];
    atomicAdd(&agg[dst * 16 + j], v);
}

// Fused per-layer MLP: Z2 = relu(relu(A @ Wa + ba) @ Wb + bb), and
// accumulates per-column sum/sumsq of Z2 into stats[0:64)/[64:128).
// 256 threads, block tile 128 rows x 64 cols, thread tile 8x4.
// Vectorized: per 4-k chunk, 8 LDS.128 (A) + 4 LDS.128 (W) feed 128 FFMA.
__global__ void __launch_bounds__(256) k_gin_mlp(
        const float* __restrict__ A,
        const float* __restrict__ Wa, const float* __restrict__ ba,
        const float* __restrict__ Wb, const float* __restrict__ bb,
        float* __restrict__ Z2, float* __restrict__ stats, int rows) {
    __shared__ float Ws[64][64];   // [k][col]
    __shared__ float As[128][68];  // [row][k], 68 keeps 16B align + kills conflicts
    __shared__ float s_sum[64], s_sq[64];
    int t = threadIdx.x;
    int row0 = blockIdx.x * 128;

    // load Wa
    for (int i = t; i < 1024; i += 256)
        ((float4*)Ws)[i] = ((const float4*)Wa)[i];
    // load A tile
    for (int i = t; i < 2048; i += 256) {
        int r = i >> 4, kc = i & 15;
        float4 v = make_float4(0.f, 0.f, 0.f, 0.f);
        if (row0 + r < rows) v = ((const float4*)A)[(row0 + r) * 16 + kc];
        *(float4*)&As[r][kc * 4] = v;
    }
    if (t < 64) { s_sum[t] = 0.f; s_sq[t] = 0.f; }
    __syncthreads();

    int tx = t & 15;   // cols cb..cb+3
    int ty = t >> 4;   // rows rb..rb+7
    int cb = tx * 4;
    int rb = ty * 8;

    float acc[8][4];
    {
        float4 bv = *(const float4*)&ba[cb];
#pragma unroll
        for (int i = 0; i < 8; i++) {
            acc[i][0] = bv.x; acc[i][1] = bv.y; acc[i][2] = bv.z; acc[i][3] = bv.w;
        }
    }

    // ---- GEMM1 ----
#pragma unroll
    for (int k0 = 0; k0 < 64; k0 += 4) {
        float4 w0 = *(float4*)&Ws[k0 + 0][cb];
        float4 w1 = *(float4*)&Ws[k0 + 1][cb];
        float4 w2 = *(float4*)&Ws[k0 + 2][cb];
        float4 w3 = *(float4*)&Ws[k0 + 3][cb];
#pragma unroll
        for (int i = 0; i < 8; i++) {
            float4 a = *(float4*)&As[rb + i][k0];
            acc[i][0] += a.x * w0.x; acc[i][1] += a.x * w0.y; acc[i][2] += a.x * w0.z; acc[i][3] += a.x * w0.w;
            acc[i][0] += a.y * w1.x; acc[i][1] += a.y * w1.y; acc[i][2] += a.y * w1.z; acc[i][3] += a.y * w1.w;
            acc[i][0] += a.z * w2.x; acc[i][1] += a.z * w2.y; acc[i][2] += a.z * w2.z; acc[i][3] += a.z * w2.w;
            acc[i][0] += a.w * w3.x; acc[i][1] += a.w * w3.y; acc[i][2] += a.w * w3.z; acc[i][3] += a.w * w3.w;
        }
    }
    __syncthreads();   // done reading As/Ws for GEMM1

    // write relu(z1) tile back into As ([row][k] with k = output col of GEMM1)
#pragma unroll
    for (int i = 0; i < 8; i++) {
        float4 v = make_float4(fmaxf(acc[i][0], 0.f), fmaxf(acc[i][1], 0.f),
                               fmaxf(acc[i][2], 0.f), fmaxf(acc[i][3], 0.f));
        *(float4*)&As[rb + i][cb] = v;
    }
    // load Wb
    for (int i = t; i < 1024; i += 256)
        ((float4*)Ws)[i] = ((const float4*)Wb)[i];
    __syncthreads();

    {
        float4 bv = *(const float4*)&bb[cb];
#pragma unroll
        for (int i = 0; i < 8; i++) {
            acc[i][0] = bv.x; acc[i][1] = bv.y; acc[i][2] = bv.z; acc[i][3] = bv.w;
        }
    }

    // ---- GEMM2 ----
#pragma unroll
    for (int k0 = 0; k0 < 64; k0 += 4) {
        float4 w0 = *(float4*)&Ws[k0 + 0][cb];
        float4 w1 = *(float4*)&Ws[k0 + 1][cb];
        float4 w2 = *(float4*)&Ws[k0 + 2][cb];
        float4 w3 = *(float4*)&Ws[k0 + 3][cb];
#pragma unroll
        for (int i = 0; i < 8; i++) {
            float4 a = *(float4*)&As[rb + i][k0];
            acc[i][0] += a.x * w0.x; acc[i][1] += a.x * w0.y; acc[i][2] += a.x * w0.z; acc[i][3] += a.x * w0.w;
            acc[i][0] += a.y * w1.x; acc[i][1] += a.y * w1.y; acc[i][2] += a.y * w1.z; acc[i][3] += a.y * w1.w;
            acc[i][0] += a.z * w2.x; acc[i][1] += a.z * w2.y; acc[i][2] += a.z * w2.z; acc[i][3] += a.z * w2.w;
            acc[i][0] += a.w * w3.x; acc[i][1] += a.w * w3.y; acc[i][2] += a.w * w3.z; acc[i][3] += a.w * w3.w;
        }
    }

    // ---- epilogue: relu, store, per-column stats ----
    float s[4] = {0.f, 0.f, 0.f, 0.f};
    float q[4] = {0.f, 0.f, 0.f, 0.f};
#pragma unroll
    for (int i = 0; i < 8; i++) {
        int r = row0 + rb + i;
        float4 v = make_float4(fmaxf(acc[i][0], 0.f), fmaxf(acc[i][1], 0.f),
                               fmaxf(acc[i][2], 0.f), fmaxf(acc[i][3], 0.f));
        if (r < rows) {
            *(float4*)&Z2[r * 64 + cb] = v;
            s[0] += v.x; q[0] += v.x * v.x;
            s[1] += v.y; q[1] += v.y * v.y;
            s[2] += v.z; q[2] += v.z * v.z;
            s[3] += v.w; q[3] += v.w * v.w;
        }
    }
    // lanes l and l+16 share the same cb -> combine, then shared atomics
#pragma unroll
    for (int j = 0; j < 4; j++) {
        s[j] += __shfl_down_sync(0xffffffff, s[j], 16);
        q[j] += __shfl_down_sync(0xffffffff, q[j], 16);
    }
    if ((t & 31) < 16) {
#pragma unroll
        for (int j = 0; j < 4; j++) {
            atomicAdd(&s_sum[cb + j], s[j]);
            atomicAdd(&s_sq[cb + j], q[j]);
        }
    }
    __syncthreads();
    if (t < 64) {
        atomicAdd(&stats[t], s_sum[t]);
        atomicAdd(&stats[64 + t], s_sq[t]);
    }
}

// stats -> scale/shift
__global__ void k_bnfinal(float* __restrict__ stats,
                          const float* __restrict__ gamma,
                          const float* __restrict__ beta) {
    int c = threadIdx.x;
    if (c >= 64) return;
    float mean = stats[c] * (1.0f / NN);
    float var  = stats[64 + c] * (1.0f / NN) - mean * mean;
    float sc = gamma[c] * rsqrtf(var + BN_EPS);
    stats[c] = sc;
    stats[64 + c] = beta[c] - mean * sc;
}

// hout = Z*scale + shift (float4); optionally also seed next layer's agg
__global__ void k_bnapply(const float4* __restrict__ Z, const float* __restrict__ stats,
                          float4* __restrict__ hout, float4* __restrict__ aggout) {
    int i = blockIdx.x * blockDim.x + threadIdx.x;
    if (i >= NN * 16) return;
    int c = (i & 15) * 4;
    float4 z = Z[i];
    float4 v = make_float4(z.x * stats[c + 0] + stats[64 + c + 0],
                           z.y * stats[c + 1] + stats[64 + c + 1],
                           z.z * stats[c + 2] + stats[64 + c + 2],
                           z.w * stats[c + 3] + stats[64 + c + 3]);
    hout[i] = v;
    if (aggout) aggout[i] = v;
}

// pool[batch[n]] += h[n]
__global__ void k_pool(const float4* __restrict__ h, const int* __restrict__ batch,
                       float4* __restrict__ pool) {
    int t = blockIdx.x * blockDim.x + threadIdx.x;
    if (t >= NN * 16) return;
    int n = t >> 4;
    int j = t & 15;
    atomicAdd(&pool[batch[n] * 16 + j], h[n * 16 + j]);
}

// tiny tail GEMMs: C[rows,M] = (relu?)(A[rows,K] @ W[K,M] + b)
template <int K, int M, bool RELU>
__global__ void k_smallgemm(const float* __restrict__ A, const float* __restrict__ W,
                            const float* __restrict__ b, float* __restrict__ C, int rows) {
    int idx = blockIdx.x * blockDim.x + threadIdx.x;
    if (idx >= rows * M) return;
    int r = idx / M, c = idx % M;
    float acc = b[c];
#pragma unroll 8
    for (int k = 0; k < K; k++) acc += A[r * K + k] * W[k * M + c];
    C[idx] = RELU ? fmaxf(acc, 0.0f) : acc;
}

// ---------------- launch ----------------

extern "C" void kernel_launch(void* const* d_in, const int* in_sizes, int n_in,
                              void* d_out, int out_size) {
    const float* x     = (const float*)d_in[0];
    const int*   ei    = (const int*)d_in[1];
    const int*   batch = (const int*)d_in[2];
    const float* prm[22];
    for (int i = 0; i < 22; i++) prm[i] = (const float*)d_in[3 + i];
    // per layer L at 6L: w_a,b_a,w_b,b_b,gamma,beta ; 18..21: w_lin0,b_lin0,w_fc1,b_fc1

    float *agg, *z2, *hA, *hB, *stats, *pool, *mid;
    cudaGetSymbolAddress((void**)&agg,   g_agg);
    cudaGetSymbolAddress((void**)&z2,    g_z2);
    cudaGetSymbolAddress((void**)&hA,    g_hA);
    cudaGetSymbolAddress((void**)&hB,    g_hB);
    cudaGetSymbolAddress((void**)&stats, g_stats);
    cudaGetSymbolAddress((void**)&pool,  g_pool);
    cudaGetSymbolAddress((void**)&mid,   g_mid);

    const int GEMM_BLOCKS = (NN + 127) / 128;     // 391
    const int SCAT_BLOCKS = (NE * 16) / 256;      // 50000
    const int CPY_BLOCKS  = (NN * 16 + 255) / 256;

    // -------- layer 1 (input x) --------
    k_copy4<<<CPY_BLOCKS, 256>>>((const float4*)x, (float4*)agg, NN * 16);
    k_scatter<<<SCAT_BLOCKS, 256>>>(ei, (const float4*)x, (float4*)agg);
    k_zero<<<1, 128>>>(stats, 128);
    k_gin_mlp<<<GEMM_BLOCKS, 256>>>(agg, prm[0], prm[1], prm[2], prm[3], z2, stats, NN);
    k_bnfinal<<<1, 64>>>(stats, prm[4], prm[5]);
    k_bnapply<<<CPY_BLOCKS, 256>>>((const float4*)z2, stats, (float4*)hA, (float4*)agg);

    // -------- layer 2 --------
    k_scatter<<<SCAT_BLOCKS, 256>>>(ei, (const float4*)hA, (float4*)agg);
    k_zero<<<1, 128>>>(stats, 128);
    k_gin_mlp<<<GEMM_BLOCKS, 256>>>(agg, prm[6], prm[7], prm[8], prm[9], z2, stats, NN);
    k_bnfinal<<<1, 64>>>(stats, prm[10], prm[11]);
    k_bnapply<<<CPY_BLOCKS, 256>>>((const float4*)z2, stats, (float4*)hB, (float4*)agg);

    // -------- layer 3 --------
    k_scatter<<<SCAT_BLOCKS, 256>>>(ei, (const float4*)hB, (float4*)agg);
    k_zero<<<1, 128>>>(stats, 128);
    k_gin_mlp<<<GEMM_BLOCKS, 256>>>(agg, prm[12], prm[13], prm[14], prm[15], z2, stats, NN);
    k_bnfinal<<<1, 64>>>(stats, prm[16], prm[17]);
    k_bnapply<<<CPY_BLOCKS, 256>>>((const float4*)z2, stats, (float4*)hA, nullptr);

    // -------- pool + head --------
    k_zero<<<(NGR * 64 + 255) / 256, 256>>>(pool, NGR * 64);
    k_pool<<<CPY_BLOCKS, 256>>>((const float4*)hA, batch, (float4*)pool);
    k_smallgemm<64, 128, false><<<(NGR * 128 + 255) / 256, 256>>>(pool, prm[18], prm[19], mid, NGR);
    k_smallgemm<128, 64, true><<<(NGR * 64 + 255) / 256, 256>>>(mid, prm[20], prm[21], (float*)d_out, NGR);
}

// round 5
// speedup vs baseline: 2.5704x; 1.0696x over previous
#include <cuda_runtime.h>
#include <cstdint>

#define NN 50000
#define NE 800000
#define NGR 512
#define BN_EPS 1e-5f

// ---------------- scratch (static __device__ — no allocations) ----------------
__device__ float4 g_agg[NN * 16];
__device__ float4 g_z2 [NN * 16];
__device__ float4 g_hA [NN * 16];
__device__ float4 g_hB [NN * 16];
__device__ float  g_stats[128];        // [0:64) sum -> scale, [64:128) sumsq -> shift
__device__ float4 g_pool[NGR * 16];
__device__ float  g_mid [NGR * 128];

// packed fp32x2 FMA (Blackwell family-level instruction, not an 'a' feature)
__device__ __forceinline__ void fma2(unsigned long long& acc,
                                     unsigned long long a,
                                     unsigned long long b) {
    asm("fma.rn.f32x2 %0, %1, %2, %0;" : "+l"(acc) : "l"(a), "l"(b));
}
__device__ __forceinline__ float fma2_reduce(unsigned long long acc) {
    float lo = __uint_as_float((uint32_t)acc);
    float hi = __uint_as_float((uint32_t)(acc >> 32));
    return lo + hi;
}

// ---------------- kernels ----------------

__global__ void k_copy4(const float4* __restrict__ src, float4* __restrict__ dst, int n) {
    int i = blockIdx.x * blockDim.x + threadIdx.x;
    if (i < n) dst[i] = src[i];
}

__global__ void k_zero(float* __restrict__ p, int n) {
    int i = blockIdx.x * blockDim.x + threadIdx.x;
    if (i < n) p[i] = 0.0f;
}

__global__ void k_scatter(const int* __restrict__ ei,
                          const float4* __restrict__ h,
                          float4* __restrict__ agg) {
    int t = blockIdx.x * blockDim.x + threadIdx.x;
    if (t >= NE * 16) return;
    int e = t >> 4;
    int j = t & 15;
    int src = ei[e];
    int dst = ei[NE + e];
    float4 v = h[src * 16 + j];
    atomicAdd(&agg[dst * 16 + j], v);
}

// Fused per-layer MLP using packed f32x2 FMAs.
// Z2 = relu(relu(A @ Wa + ba) @ Wb + bb); also accumulates column sum/sumsq into stats.
// 256 threads; block tile 128 rows x 64 cols; thread tile 8 rows x 4 cols
// with cols c = tx + 16j (lane-contiguous W loads, conflict-free).
// f32x2 lanes hold (even-k, odd-k) partial sums; reduced in epilogue.
__global__ void __launch_bounds__(256) k_gin_mlp(
        const float* __restrict__ A,
        const float* __restrict__ Wa, const float* __restrict__ ba,
        const float* __restrict__ Wb, const float* __restrict__ bb,
        float* __restrict__ Z2, float* __restrict__ stats, int rows) {
    __shared__ float As[128][68];     // [row][k], 272B rows (16B aligned), broadcast reads
    __shared__ float4 Wc[16][64];     // [k/4][col] = (W[4kk..4kk+3][col]) ; 16 KB
    __shared__ float s_sum[64], s_sq[64], sbias_a[64], sbias_b[64];

    const int t = threadIdx.x;
    const int tx = t & 15;            // cols tx, tx+16, tx+32, tx+48
    const int ty = t >> 4;            // rows rb..rb+7
    const int rb = ty * 8;
    const int row0 = blockIdx.x * 128;

    // load Wa transposed-packed: Wc[kk][c] = {Wa[4kk][c], Wa[4kk+1][c], Wa[4kk+2][c], Wa[4kk+3][c]}
    for (int i = t; i < 1024; i += 256) {
        int kk = i >> 6, c = i & 63;
        Wc[kk][c] = make_float4(Wa[(4 * kk + 0) * 64 + c], Wa[(4 * kk + 1) * 64 + c],
                                Wa[(4 * kk + 2) * 64 + c], Wa[(4 * kk + 3) * 64 + c]);
    }
    // load A tile
    for (int i = t; i < 2048; i += 256) {
        int r = i >> 4, kc = i & 15;
        float4 v = make_float4(0.f, 0.f, 0.f, 0.f);
        if (row0 + r < rows) v = ((const float4*)A)[(row0 + r) * 16 + kc];
        *(float4*)&As[r][kc * 4] = v;
    }
    if (t < 64) { s_sum[t] = 0.f; s_sq[t] = 0.f; sbias_a[t] = ba[t]; sbias_b[t] = bb[t]; }
    __syncthreads();

    unsigned long long acc[8][4];
#pragma unroll
    for (int i = 0; i < 8; i++)
#pragma unroll
        for (int j = 0; j < 4; j++) acc[i][j] = 0ull;

    // ---- GEMM1 ----
#pragma unroll 4
    for (int kk = 0; kk < 16; kk++) {
        ulonglong2 w[4];
#pragma unroll
        for (int j = 0; j < 4; j++)
            w[j] = *(const ulonglong2*)&Wc[kk][tx + 16 * j];
#pragma unroll
        for (int i = 0; i < 8; i++) {
            ulonglong2 a = *(const ulonglong2*)&As[rb + i][kk * 4];
#pragma unroll
            for (int j = 0; j < 4; j++) {
                fma2(acc[i][j], a.x, w[j].x);
                fma2(acc[i][j], a.y, w[j].y);
            }
        }
    }
    __syncthreads();   // all GEMM1 reads of As/Wc done

    // ---- epilogue 1: z1 = relu(.) -> As[row][col], reload Wc with Wb ----
#pragma unroll
    for (int i = 0; i < 8; i++) {
#pragma unroll
        for (int j = 0; j < 4; j++) {
            int c = tx + 16 * j;
            float v = fmaxf(fma2_reduce(acc[i][j]) + sbias_a[c], 0.f);
            As[rb + i][c] = v;
            acc[i][j] = 0ull;
        }
    }
    for (int i = t; i < 1024; i += 256) {
        int kk = i >> 6, c = i & 63;
        Wc[kk][c] = make_float4(Wb[(4 * kk + 0) * 64 + c], Wb[(4 * kk + 1) * 64 + c],
                                Wb[(4 * kk + 2) * 64 + c], Wb[(4 * kk + 3) * 64 + c]);
    }
    __syncthreads();

    // ---- GEMM2 ----
#pragma unroll 4
    for (int kk = 0; kk < 16; kk++) {
        ulonglong2 w[4];
#pragma unroll
        for (int j = 0; j < 4; j++)
            w[j] = *(const ulonglong2*)&Wc[kk][tx + 16 * j];
#pragma unroll
        for (int i = 0; i < 8; i++) {
            ulonglong2 a = *(const ulonglong2*)&As[rb + i][kk * 4];
#pragma unroll
            for (int j = 0; j < 4; j++) {
                fma2(acc[i][j], a.x, w[j].x);
                fma2(acc[i][j], a.y, w[j].y);
            }
        }
    }

    // ---- epilogue 2: relu, store Z2, column stats ----
    float s[4] = {0.f, 0.f, 0.f, 0.f};
    float q[4] = {0.f, 0.f, 0.f, 0.f};
#pragma unroll
    for (int i = 0; i < 8; i++) {
        int r = row0 + rb + i;
        if (r < rows) {
#pragma unroll
            for (int j = 0; j < 4; j++) {
                int c = tx + 16 * j;
                float v = fmaxf(fma2_reduce(acc[i][j]) + sbias_b[c], 0.f);
                Z2[r * 64 + c] = v;
                s[j] += v;
                q[j] += v * v;
            }
        }
    }
    // lanes l and l+16 share the same tx (same cols) -> combine, then shared atomics
#pragma unroll
    for (int j = 0; j < 4; j++) {
        s[j] += __shfl_down_sync(0xffffffff, s[j], 16);
        q[j] += __shfl_down_sync(0xffffffff, q[j], 16);
    }
    if ((t & 31) < 16) {
#pragma unroll
        for (int j = 0; j < 4; j++) {
            atomicAdd(&s_sum[tx + 16 * j], s[j]);
            atomicAdd(&s_sq[tx + 16 * j], q[j]);
        }
    }
    __syncthreads();
    if (t < 64) {
        atomicAdd(&stats[t], s_sum[t]);
        atomicAdd(&stats[64 + t], s_sq[t]);
    }
}

// stats -> scale/shift
__global__ void k_bnfinal(float* __restrict__ stats,
                          const float* __restrict__ gamma,
                          const float* __restrict__ beta) {
    int c = threadIdx.x;
    if (c >= 64) return;
    float mean = stats[c] * (1.0f / NN);
    float var  = stats[64 + c] * (1.0f / NN) - mean * mean;
    float sc = gamma[c] * rsqrtf(var + BN_EPS);
    stats[c] = sc;
    stats[64 + c] = beta[c] - mean * sc;
}

__global__ void k_bnapply(const float4* __restrict__ Z, const float* __restrict__ stats,
                          float4* __restrict__ hout, float4* __restrict__ aggout) {
    int i = blockIdx.x * blockDim.x + threadIdx.x;
    if (i >= NN * 16) return;
    int c = (i & 15) * 4;
    float4 z = Z[i];
    float4 v = make_float4(z.x * stats[c + 0] + stats[64 + c + 0],
                           z.y * stats[c + 1] + stats[64 + c + 1],
                           z.z * stats[c + 2] + stats[64 + c + 2],
                           z.w * stats[c + 3] + stats[64 + c + 3]);
    hout[i] = v;
    if (aggout) aggout[i] = v;
}

__global__ void k_pool(const float4* __restrict__ h, const int* __restrict__ batch,
                       float4* __restrict__ pool) {
    int t = blockIdx.x * blockDim.x + threadIdx.x;
    if (t >= NN * 16) return;
    int n = t >> 4;
    int j = t & 15;
    atomicAdd(&pool[batch[n] * 16 + j], h[n * 16 + j]);
}

template <int K, int M, bool RELU>
__global__ void k_smallgemm(const float* __restrict__ A, const float* __restrict__ W,
                            const float* __restrict__ b, float* __restrict__ C, int rows) {
    int idx = blockIdx.x * blockDim.x + threadIdx.x;
    if (idx >= rows * M) return;
    int r = idx / M, c = idx % M;
    float acc = b[c];
#pragma unroll 8
    for (int k = 0; k < K; k++) acc += A[r * K + k] * W[k * M + c];
    C[idx] = RELU ? fmaxf(acc, 0.0f) : acc;
}

// ---------------- launch ----------------

extern "C" void kernel_launch(void* const* d_in, const int* in_sizes, int n_in,
                              void* d_out, int out_size) {
    const float* x     = (const float*)d_in[0];
    const int*   ei    = (const int*)d_in[1];
    const int*   batch = (const int*)d_in[2];
    const float* prm[22];
    for (int i = 0; i < 22; i++) prm[i] = (const float*)d_in[3 + i];
    // per layer L at 6L: w_a,b_a,w_b,b_b,gamma,beta ; 18..21: w_lin0,b_lin0,w_fc1,b_fc1

    float *agg, *z2, *hA, *hB, *stats, *pool, *mid;
    cudaGetSymbolAddress((void**)&agg,   g_agg);
    cudaGetSymbolAddress((void**)&z2,    g_z2);
    cudaGetSymbolAddress((void**)&hA,    g_hA);
    cudaGetSymbolAddress((void**)&hB,    g_hB);
    cudaGetSymbolAddress((void**)&stats, g_stats);
    cudaGetSymbolAddress((void**)&pool,  g_pool);
    cudaGetSymbolAddress((void**)&mid,   g_mid);

    const int MLP_BLOCKS  = (NN + 127) / 128;     // 391
    const int SCAT_BLOCKS = (NE * 16) / 256;
    const int CPY_BLOCKS  = (NN * 16 + 255) / 256;

    // -------- layer 1 (input x) --------
    k_copy4<<<CPY_BLOCKS, 256>>>((const float4*)x, (float4*)agg, NN * 16);
    k_scatter<<<SCAT_BLOCKS, 256>>>(ei, (const float4*)x, (float4*)agg);
    k_zero<<<1, 128>>>(stats, 128);
    k_gin_mlp<<<MLP_BLOCKS, 256>>>(agg, prm[0], prm[1], prm[2], prm[3], z2, stats, NN);
    k_bnfinal<<<1, 64>>>(stats, prm[4], prm[5]);
    k_bnapply<<<CPY_BLOCKS, 256>>>((const float4*)z2, stats, (float4*)hA, (float4*)agg);

    // -------- layer 2 --------
    k_scatter<<<SCAT_BLOCKS, 256>>>(ei, (const float4*)hA, (float4*)agg);
    k_zero<<<1, 128>>>(stats, 128);
    k_gin_mlp<<<MLP_BLOCKS, 256>>>(agg, prm[6], prm[7], prm[8], prm[9], z2, stats, NN);
    k_bnfinal<<<1, 64>>>(stats, prm[10], prm[11]);
    k_bnapply<<<CPY_BLOCKS, 256>>>((const float4*)z2, stats, (float4*)hB, (float4*)agg);

    // -------- layer 3 --------
    k_scatter<<<SCAT_BLOCKS, 256>>>(ei, (const float4*)hB, (float4*)agg);
    k_zero<<<1, 128>>>(stats, 128);
    k_gin_mlp<<<MLP_BLOCKS, 256>>>(agg, prm[12], prm[13], prm[14], prm[15], z2, stats, NN);
    k_bnfinal<<<1, 64>>>(stats, prm[16], prm[17]);
    k_bnapply<<<CPY_BLOCKS, 256>>>((const float4*)z2, stats, (float4*)hA, nullptr);

    // -------- pool + head --------
    k_zero<<<(NGR * 64 + 255) / 256, 256>>>(pool, NGR * 64);
    k_pool<<<CPY_BLOCKS, 256>>>((const float4*)hA, batch, (float4*)pool);
    k_smallgemm<64, 128, false><<<(NGR * 128 + 255) / 256, 256>>>(pool, prm[18], prm[19], mid, NGR);
    k_smallgemm<128, 64, true><<<(NGR * 64 + 255) / 256, 256>>>(mid, prm[20], prm[21], (float*)d_out, NGR);
}

// round 6
// speedup vs baseline: 2.6144x; 1.0171x over previous
#include <cuda_runtime.h>
#include <cstdint>

#define NN 50000
#define NE 800000
#define NGR 512
#define BN_EPS 1e-5f

// ---------------- scratch (static __device__ — no allocations) ----------------
__device__ float4 g_agg[NN * 16];
__device__ float4 g_z2 [NN * 16];
__device__ float4 g_hA [NN * 16];
__device__ float4 g_hB [NN * 16];
__device__ float  g_stats[384];          // 3 layers x (sum[64], sumsq[64])
__device__ float4 g_pool[NGR * 16];
__device__ float  g_mid [NGR * 128];
__device__ int    g_deg[NN];
__device__ int    g_rowptr[NN + 1];
__device__ int    g_cursor[NN];
__device__ int    g_csr[NE];

// packed fp32x2 FMA (Blackwell family-level instruction, not an 'a' feature)
__device__ __forceinline__ void fma2(unsigned long long& acc,
                                     unsigned long long a,
                                     unsigned long long b) {
    asm("fma.rn.f32x2 %0, %1, %2, %0;" : "+l"(acc) : "l"(a), "l"(b));
}
__device__ __forceinline__ float fma2_reduce(unsigned long long acc) {
    float lo = __uint_as_float((uint32_t)acc);
    float hi = __uint_as_float((uint32_t)(acc >> 32));
    return lo + hi;
}

// ---------------- CSR build ----------------

__global__ void k_init(int* __restrict__ deg, float* __restrict__ stats,
                       float* __restrict__ pool) {
    int i = blockIdx.x * blockDim.x + threadIdx.x;
    if (i < NN) deg[i] = 0;
    if (i < 384) stats[i] = 0.0f;
    if (i < NGR * 64) pool[i] = 0.0f;
}

__global__ void k_hist(const int* __restrict__ ei, int* __restrict__ deg) {
    int e = blockIdx.x * blockDim.x + threadIdx.x;
    if (e < NE) atomicAdd(&deg[ei[NE + e]], 1);
}

// single-block exclusive scan over deg -> rowptr/cursor
__global__ void k_scan(const int* __restrict__ deg, int* __restrict__ rowptr,
                       int* __restrict__ cursor) {
    __shared__ int part[1024];
    const int t = threadIdx.x;
    const int CH = (NN + 1023) / 1024;             // 49
    int start = t * CH;
    int end = start + CH; if (end > NN) end = NN;
    int s = 0;
    for (int i = start; i < end; i++) s += deg[i];
    part[t] = s;
    __syncthreads();
    for (int off = 1; off < 1024; off <<= 1) {
        int v = part[t];
        int add = (t >= off) ? part[t - off] : 0;
        __syncthreads();
        part[t] = v + add;
        __syncthreads();
    }
    int run = (t > 0) ? part[t - 1] : 0;
    for (int i = start; i < end; i++) {
        rowptr[i] = run;
        cursor[i] = run;
        run += deg[i];
    }
    if (t == 1023) rowptr[NN] = run;               // == NE
}

__global__ void k_fill(const int* __restrict__ ei, int* __restrict__ cursor,
                       int* __restrict__ csr) {
    int e = blockIdx.x * blockDim.x + threadIdx.x;
    if (e >= NE) return;
    int pos = atomicAdd(&cursor[ei[NE + e]], 1);
    csr[pos] = ei[e];
}

// pull-gather: out[n] = h[n] + sum_{s in N(n)} h[s]   (no atomics)
__global__ void k_gather(const float4* __restrict__ h,
                         const int* __restrict__ rowptr,
                         const int* __restrict__ csr,
                         float4* __restrict__ out) {
    int t = blockIdx.x * blockDim.x + threadIdx.x;
    if (t >= NN * 16) return;
    int n = t >> 4;
    int j = t & 15;
    float4 acc = h[n * 16 + j];
    int b = rowptr[n], e = rowptr[n + 1];
    for (int idx = b; idx < e; idx++) {
        int s = __ldg(&csr[idx]);                  // broadcast across the 16 slice-threads
        float4 v = h[s * 16 + j];
        acc.x += v.x; acc.y += v.y; acc.z += v.z; acc.w += v.w;
    }
    out[t] = acc;
}

// ---------------- fused MLP (unchanged from R5) ----------------
__global__ void __launch_bounds__(256) k_gin_mlp(
        const float* __restrict__ A,
        const float* __restrict__ Wa, const float* __restrict__ ba,
        const float* __restrict__ Wb, const float* __restrict__ bb,
        float* __restrict__ Z2, float* __restrict__ stats, int rows) {
    __shared__ float As[128][68];
    __shared__ float4 Wc[16][64];
    __shared__ float s_sum[64], s_sq[64], sbias_a[64], sbias_b[64];

    const int t = threadIdx.x;
    const int tx = t & 15;
    const int ty = t >> 4;
    const int rb = ty * 8;
    const int row0 = blockIdx.x * 128;

    for (int i = t; i < 1024; i += 256) {
        int kk = i >> 6, c = i & 63;
        Wc[kk][c] = make_float4(Wa[(4 * kk + 0) * 64 + c], Wa[(4 * kk + 1) * 64 + c],
                                Wa[(4 * kk + 2) * 64 + c], Wa[(4 * kk + 3) * 64 + c]);
    }
    for (int i = t; i < 2048; i += 256) {
        int r = i >> 4, kc = i & 15;
        float4 v = make_float4(0.f, 0.f, 0.f, 0.f);
        if (row0 + r < rows) v = ((const float4*)A)[(row0 + r) * 16 + kc];
        *(float4*)&As[r][kc * 4] = v;
    }
    if (t < 64) { s_sum[t] = 0.f; s_sq[t] = 0.f; sbias_a[t] = ba[t]; sbias_b[t] = bb[t]; }
    __syncthreads();

    unsigned long long acc[8][4];
#pragma unroll
    for (int i = 0; i < 8; i++)
#pragma unroll
        for (int j = 0; j < 4; j++) acc[i][j] = 0ull;

#pragma unroll 4
    for (int kk = 0; kk < 16; kk++) {
        ulonglong2 w[4];
#pragma unroll
        for (int j = 0; j < 4; j++)
            w[j] = *(const ulonglong2*)&Wc[kk][tx + 16 * j];
#pragma unroll
        for (int i = 0; i < 8; i++) {
            ulonglong2 a = *(const ulonglong2*)&As[rb + i][kk * 4];
#pragma unroll
            for (int j = 0; j < 4; j++) {
                fma2(acc[i][j], a.x, w[j].x);
                fma2(acc[i][j], a.y, w[j].y);
            }
        }
    }
    __syncthreads();

#pragma unroll
    for (int i = 0; i < 8; i++) {
#pragma unroll
        for (int j = 0; j < 4; j++) {
            int c = tx + 16 * j;
            float v = fmaxf(fma2_reduce(acc[i][j]) + sbias_a[c], 0.f);
            As[rb + i][c] = v;
            acc[i][j] = 0ull;
        }
    }
    for (int i = t; i < 1024; i += 256) {
        int kk = i >> 6, c = i & 63;
        Wc[kk][c] = make_float4(Wb[(4 * kk + 0) * 64 + c], Wb[(4 * kk + 1) * 64 + c],
                                Wb[(4 * kk + 2) * 64 + c], Wb[(4 * kk + 3) * 64 + c]);
    }
    __syncthreads();

#pragma unroll 4
    for (int kk = 0; kk < 16; kk++) {
        ulonglong2 w[4];
#pragma unroll
        for (int j = 0; j < 4; j++)
            w[j] = *(const ulonglong2*)&Wc[kk][tx + 16 * j];
#pragma unroll
        for (int i = 0; i < 8; i++) {
            ulonglong2 a = *(const ulonglong2*)&As[rb + i][kk * 4];
#pragma unroll
            for (int j = 0; j < 4; j++) {
                fma2(acc[i][j], a.x, w[j].x);
                fma2(acc[i][j], a.y, w[j].y);
            }
        }
    }

    float s[4] = {0.f, 0.f, 0.f, 0.f};
    float q[4] = {0.f, 0.f, 0.f, 0.f};
#pragma unroll
    for (int i = 0; i < 8; i++) {
        int r = row0 + rb + i;
        if (r < rows) {
#pragma unroll
            for (int j = 0; j < 4; j++) {
                int c = tx + 16 * j;
                float v = fmaxf(fma2_reduce(acc[i][j]) + sbias_b[c], 0.f);
                Z2[r * 64 + c] = v;
                s[j] += v;
                q[j] += v * v;
            }
        }
    }
#pragma unroll
    for (int j = 0; j < 4; j++) {
        s[j] += __shfl_down_sync(0xffffffff, s[j], 16);
        q[j] += __shfl_down_sync(0xffffffff, q[j], 16);
    }
    if ((t & 31) < 16) {
#pragma unroll
        for (int j = 0; j < 4; j++) {
            atomicAdd(&s_sum[tx + 16 * j], s[j]);
            atomicAdd(&s_sq[tx + 16 * j], q[j]);
        }
    }
    __syncthreads();
    if (t < 64) {
        atomicAdd(&stats[t], s_sum[t]);
        atomicAdd(&stats[64 + t], s_sq[t]);
    }
}

// ---------------- BN apply (bnfinal fused per block); optional pool fusion ----------------
__global__ void k_bn(const float4* __restrict__ Z, const float* __restrict__ stats,
                     const float* __restrict__ gamma, const float* __restrict__ beta,
                     float4* __restrict__ hout,
                     const int* __restrict__ batch, float4* __restrict__ pool) {
    __shared__ float sc[64], sh[64];
    int t = threadIdx.x;
    if (t < 64) {
        float mean = stats[t] * (1.0f / NN);
        float var  = stats[64 + t] * (1.0f / NN) - mean * mean;
        float s = gamma[t] * rsqrtf(var + BN_EPS);
        sc[t] = s;
        sh[t] = beta[t] - mean * s;
    }
    __syncthreads();
    int i = blockIdx.x * blockDim.x + t;
    if (i >= NN * 16) return;
    int c = (i & 15) * 4;
    float4 z = Z[i];
    float4 v = make_float4(z.x * sc[c + 0] + sh[c + 0],
                           z.y * sc[c + 1] + sh[c + 1],
                           z.z * sc[c + 2] + sh[c + 2],
                           z.w * sc[c + 3] + sh[c + 3]);
    if (hout) hout[i] = v;
    if (pool) atomicAdd(&pool[batch[i >> 4] * 16 + (i & 15)], v);
}

// tiny tail GEMMs
template <int K, int M, bool RELU>
__global__ void k_smallgemm(const float* __restrict__ A, const float* __restrict__ W,
                            const float* __restrict__ b, float* __restrict__ C, int rows) {
    int idx = blockIdx.x * blockDim.x + threadIdx.x;
    if (idx >= rows * M) return;
    int r = idx / M, c = idx % M;
    float acc = b[c];
#pragma unroll 8
    for (int k = 0; k < K; k++) acc += A[r * K + k] * W[k * M + c];
    C[idx] = RELU ? fmaxf(acc, 0.0f) : acc;
}

// ---------------- launch ----------------

extern "C" void kernel_launch(void* const* d_in, const int* in_sizes, int n_in,
                              void* d_out, int out_size) {
    const float* x     = (const float*)d_in[0];
    const int*   ei    = (const int*)d_in[1];
    const int*   batch = (const int*)d_in[2];
    const float* prm[22];
    for (int i = 0; i < 22; i++) prm[i] = (const float*)d_in[3 + i];
    // per layer L at 6L: w_a,b_a,w_b,b_b,gamma,beta ; 18..21: w_lin0,b_lin0,w_fc1,b_fc1

    float *agg, *z2, *hA, *hB, *stats, *pool, *mid;
    int *deg, *rowptr, *cursor, *csr;
    cudaGetSymbolAddress((void**)&agg,    g_agg);
    cudaGetSymbolAddress((void**)&z2,     g_z2);
    cudaGetSymbolAddress((void**)&hA,     g_hA);
    cudaGetSymbolAddress((void**)&hB,     g_hB);
    cudaGetSymbolAddress((void**)&stats,  g_stats);
    cudaGetSymbolAddress((void**)&pool,   g_pool);
    cudaGetSymbolAddress((void**)&mid,    g_mid);
    cudaGetSymbolAddress((void**)&deg,    g_deg);
    cudaGetSymbolAddress((void**)&rowptr, g_rowptr);
    cudaGetSymbolAddress((void**)&cursor, g_cursor);
    cudaGetSymbolAddress((void**)&csr,    g_csr);

    const int MLP_BLOCKS = (NN + 127) / 128;       // 391
    const int EDG_BLOCKS = (NE + 255) / 256;       // 3125
    const int NOD_BLOCKS = (NN * 16 + 255) / 256;  // 3125

    // -------- CSR build (once; graph shared by all 3 layers) --------
    k_init<<<(NN + 255) / 256, 256>>>(deg, stats, pool);
    k_hist<<<EDG_BLOCKS, 256>>>(ei, deg);
    k_scan<<<1, 1024>>>(deg, rowptr, cursor);
    k_fill<<<EDG_BLOCKS, 256>>>(ei, cursor, csr);

    // -------- layer 1 (input x) --------
    k_gather<<<NOD_BLOCKS, 256>>>((const float4*)x, rowptr, csr, (float4*)agg);
    k_gin_mlp<<<MLP_BLOCKS, 256>>>(agg, prm[0], prm[1], prm[2], prm[3], z2, stats, NN);
    k_bn<<<NOD_BLOCKS, 256>>>((const float4*)z2, stats, prm[4], prm[5],
                              (float4*)hA, nullptr, nullptr);

    // -------- layer 2 --------
    k_gather<<<NOD_BLOCKS, 256>>>((const float4*)hA, rowptr, csr, (float4*)agg);
    k_gin_mlp<<<MLP_BLOCKS, 256>>>(agg, prm[6], prm[7], prm[8], prm[9], z2, stats + 128, NN);
    k_bn<<<NOD_BLOCKS, 256>>>((const float4*)z2, stats + 128, prm[10], prm[11],
                              (float4*)hB, nullptr, nullptr);

    // -------- layer 3 (BN output goes straight into pool atomics) --------
    k_gather<<<NOD_BLOCKS, 256>>>((const float4*)hB, rowptr, csr, (float4*)agg);
    k_gin_mlp<<<MLP_BLOCKS, 256>>>(agg, prm[12], prm[13], prm[14], prm[15], z2, stats + 256, NN);
    k_bn<<<NOD_BLOCKS, 256>>>((const float4*)z2, stats + 256, prm[16], prm[17],
                              nullptr, batch, (float4*)pool);

    // -------- head --------
    k_smallgemm<64, 128, false><<<(NGR * 128 + 255) / 256, 256>>>((float*)pool, prm[18], prm[19], mid, NGR);
    k_smallgemm<128, 64, true><<<(NGR * 64 + 255) / 256, 256>>>(mid, prm[20], prm[21], (float*)d_out, NGR);
}